// round 12
// baseline (speedup 1.0000x reference)
#include <cuda_runtime.h>
#include <math.h>

#define NP   4096
#define NSEQ 512
#define EE   64
#define GG   128
#define KSPLIT 16

// ---------------- scratch (device globals) ---------------------------------
__device__ float g_f [NP*EE];
__device__ float g_fr[NP*EE];
__device__ float g_T1[NP*EE];
__device__ float g_T2[NP*EE];
__device__ float g_part[KSPLIT*NP*EE];
__device__ float g_s1[NP];
__device__ float g_seqc[NSEQ];
__device__ float g_w2g[EE*GG];
__device__ float g_w2t[EE*GG];
__device__ float g_Pg[NP*GG];
__device__ float g_Pt[NP*GG];
__device__ float g_Ph[NP*EE];
__device__ float g_ordv[NSEQ];
__device__ int   g_ordi[NSEQ];
__device__ int   g_first[NP];
__device__ float g_cvals[NSEQ];
__device__ int   g_specok;

// ---------------- f32x2 packed helpers -------------------------------------
__device__ __forceinline__ unsigned long long pk2(float lo, float hi) {
    unsigned long long r;
    asm("mov.b64 %0, {%1, %2};" : "=l"(r) : "f"(lo), "f"(hi));
    return r;
}
__device__ __forceinline__ void fma2(unsigned long long& d, unsigned long long a,
                                     unsigned long long b) {
    asm("fma.rn.f32x2 %0, %1, %2, %0;" : "+l"(d) : "l"(a), "l"(b));
}
__device__ __forceinline__ float2 upk(unsigned long long v) {
    float2 f;
    asm("mov.b64 {%0, %1}, %2;" : "=f"(f.x), "=f"(f.y) : "l"(v));
    return f;
}

// ---------------- fused small-kernel pass: feat | seq | fusew ---------------
__global__ void ker_init(const float* __restrict__ f, const float* __restrict__ wf,
                         const float* __restrict__ bf, const float* __restrict__ x,
                         const float* __restrict__ ws, const float* __restrict__ bs,
                         const float* __restrict__ we, const float* __restrict__ w2,
                         const float* __restrict__ wg, const float* __restrict__ wt) {
    int tid = threadIdx.x;
    int b = blockIdx.x;
    if (b < 1024) {                         // ---- feat
        __shared__ float fs[4][20];
        int r = tid >> 6, c = tid & 63;
        if (tid < 80) fs[tid / 20][tid % 20] = f[b * 80 + tid];
        __syncthreads();
        int row = b * 4 + r;
        float acc = bf[c];
#pragma unroll
        for (int a = 0; a < 20; a++) acc = fmaf(fs[r][a], wf[a * 64 + c], acc);
        g_f [row * 64 + c] = acc;
        g_fr[row * 64 + c] = fmaxf(acc, 0.f);
    } else if (b < 1056) {                  // ---- seq
        int bb = b - 1024;
        __shared__ float xv[16][20];
        __shared__ float red[16][16];
        for (int i = tid; i < 320; i += 256) xv[i / 20][i % 20] = x[bb * 320 + i];
        __syncthreads();
        int kk = tid >> 4, s = tid & 15;
        float e = bs[s];
#pragma unroll
        for (int a = 0; a < 20; a++) e = fmaf(xv[kk][a], ws[a * 16 + s], e);
        red[kk][s] = fmaxf(e, 0.f) * we[128 + s];
        __syncthreads();
        if (s == 0) {
            float t = 0.f;
#pragma unroll
            for (int q = 0; q < 16; q++) t += red[kk][q];
            g_seqc[bb * 16 + kk] = t;
        }
    } else {                                 // ---- fusew
        int o = (b - 1056) * 256 + tid;
        int which = o >> 13;
        int q = o & 8191;
        int e = q >> 7, c = q & 127;
        const float* W = which ? wt : wg;
        float acc = 0.f;
#pragma unroll
        for (int m = 0; m < 64; m++) acc = fmaf(w2[e * 64 + m], W[m * 128 + c], acc);
        if (which) g_w2t[q] = acc; else g_w2g[q] = acc;
    }
}

// ---------------- projections: Pg = F@w2g, Pt = F@w2t, Ph = F@wgcn2 --------
__global__ void __launch_bounds__(320) ker_proj(const float* __restrict__ wgcn2) {
    __shared__ float rows[8][64];
    int tid = threadIdx.x;
    int r0 = blockIdx.x * 8;
    for (int i = tid; i < 512; i += 320)
        rows[i >> 6][i & 63] = g_f[(r0 + (i >> 6)) * 64 + (i & 63)];
    __syncthreads();
    const float* W; int c, stride; float* P; int pstride;
    if (tid < 128)      { W = g_w2g; c = tid;       stride = 128; P = g_Pg; pstride = 128; }
    else if (tid < 256) { W = g_w2t; c = tid - 128; stride = 128; P = g_Pt; pstride = 128; }
    else                { W = wgcn2; c = tid - 256; stride = 64;  P = g_Ph; pstride = 64;  }
    float acc[8] = {0,0,0,0,0,0,0,0};
#pragma unroll 8
    for (int e = 0; e < 64; e++) {
        float w = W[e * stride + c];
#pragma unroll
        for (int r = 0; r < 8; r++) acc[r] = fmaf(rows[r][e], w, acc[r]);
    }
#pragma unroll
    for (int r = 0; r < 8; r++) P[(size_t)(r0 + r) * pstride + c] = acc[r];
}

// -------- C_partial = A @ B  (split-K, f32x2, R3 layout + double buffer) ----
__global__ void __launch_bounds__(128) ker_gemm64(const float* __restrict__ A, int bsel) {
    const float* __restrict__ B = (bsel == 0) ? g_fr : ((bsel == 1) ? g_T1 : g_T2);
    __shared__ float As[2][16][132];
    __shared__ float Bs[2][16][64];
    int tid = threadIdx.x;
    int tx = tid & 7, ty = tid >> 3;
    int row0 = blockIdx.x * 128;
    int k0 = blockIdx.y * 256;
    int ar = tid >> 2;
    int ak = (tid & 3) * 4;
    int bk = tid >> 3;
    int bc = (tid & 7) * 8;

    unsigned long long acc[8][4];
#pragma unroll
    for (int i = 0; i < 8; i++)
#pragma unroll
        for (int j = 0; j < 4; j++) acc[i][j] = 0ull;

    float4 av[4], bv0, bv1;
#pragma unroll
    for (int q = 0; q < 4; q++)
        av[q] = *(const float4*)&A[(size_t)(row0 + ar + 32 * q) * 4096 + (k0 + ak)];
    bv0 = *(const float4*)&B[(size_t)(k0 + bk) * 64 + bc];
    bv1 = *(const float4*)&B[(size_t)(k0 + bk) * 64 + bc + 4];
#pragma unroll
    for (int q = 0; q < 4; q++) {
        int r = ar + 32 * q;
        As[0][ak + 0][r] = av[q].x; As[0][ak + 1][r] = av[q].y;
        As[0][ak + 2][r] = av[q].z; As[0][ak + 3][r] = av[q].w;
    }
    *(float4*)&Bs[0][bk][bc]     = bv0;
    *(float4*)&Bs[0][bk][bc + 4] = bv1;
    __syncthreads();

    for (int t = 0; t < 16; t++) {
        int cur = t & 1;
        if (t < 15) {
            int kn = k0 + (t + 1) * 16;
#pragma unroll
            for (int q = 0; q < 4; q++)
                av[q] = *(const float4*)&A[(size_t)(row0 + ar + 32 * q) * 4096 + (kn + ak)];
            bv0 = *(const float4*)&B[(size_t)(kn + bk) * 64 + bc];
            bv1 = *(const float4*)&B[(size_t)(kn + bk) * 64 + bc + 4];
        }
#pragma unroll
        for (int kk = 0; kk < 16; kk++) {
            float4 a0 = *(const float4*)&As[cur][kk][ty * 8];
            float4 a1 = *(const float4*)&As[cur][kk][ty * 8 + 4];
            float4 b0 = *(const float4*)&Bs[cur][kk][tx * 8];
            float4 b1 = *(const float4*)&Bs[cur][kk][tx * 8 + 4];
            unsigned long long bp[4];
            bp[0] = pk2(b0.x, b0.y); bp[1] = pk2(b0.z, b0.w);
            bp[2] = pk2(b1.x, b1.y); bp[3] = pk2(b1.z, b1.w);
            float ar8[8] = {a0.x, a0.y, a0.z, a0.w, a1.x, a1.y, a1.z, a1.w};
#pragma unroll
            for (int i = 0; i < 8; i++) {
                unsigned long long ap = pk2(ar8[i], ar8[i]);
#pragma unroll
                for (int j = 0; j < 4; j++) fma2(acc[i][j], ap, bp[j]);
            }
        }
        if (t < 15) {
            int nxt = cur ^ 1;
#pragma unroll
            for (int q = 0; q < 4; q++) {
                int r = ar + 32 * q;
                As[nxt][ak + 0][r] = av[q].x; As[nxt][ak + 1][r] = av[q].y;
                As[nxt][ak + 2][r] = av[q].z; As[nxt][ak + 3][r] = av[q].w;
            }
            *(float4*)&Bs[nxt][bk][bc]     = bv0;
            *(float4*)&Bs[nxt][bk][bc + 4] = bv1;
            __syncthreads();
        }
    }
    float* Cp = g_part + (size_t)blockIdx.y * (NP * EE);
#pragma unroll
    for (int i = 0; i < 8; i++) {
        int row = row0 + ty * 8 + i;
        float2 c0 = upk(acc[i][0]), c1 = upk(acc[i][1]);
        float2 c2 = upk(acc[i][2]), c3 = upk(acc[i][3]);
        float* p = &Cp[(size_t)row * 64 + tx * 8];
        *(float4*)p       = make_float4(c0.x, c0.y, c1.x, c1.y);
        *(float4*)(p + 4) = make_float4(c2.x, c2.y, c3.x, c3.y);
    }
}

// ---------------- split-K reduce (float4 vectorized) ------------------------
__global__ void ker_reduce(int csel) {
    float* C = (csel == 1) ? g_T2 : g_T1;
    int i = (blockIdx.x * 256 + threadIdx.x) * 4;
    float4 s = *(const float4*)&g_part[i];
#pragma unroll
    for (int q = 1; q < KSPLIT; q++) {
        float4 v = *(const float4*)&g_part[(size_t)q * (NP * EE) + i];
        s.x += v.x; s.y += v.y; s.z += v.z; s.w += v.w;
    }
    *(float4*)&C[i] = s;
}

// ------------- fused: reduce partials of GEMM3 + s1 computation -------------
__global__ void ker_h1s1(const float* __restrict__ w1, const float* __restrict__ we) {
    __shared__ float t[4][64];
    __shared__ float rv[4][64];
    int tid = threadIdx.x;
    int r = tid >> 6, c = tid & 63;
    int row = blockIdx.x * 4 + r;
    size_t off = (size_t)row * 64 + c;
    float s = 0.f;
#pragma unroll
    for (int q = 0; q < KSPLIT; q++) s += g_part[(size_t)q * (NP * EE) + off];
    t[r][c] = s;
    __syncthreads();
    float h = 0.f;
#pragma unroll
    for (int e = 0; e < 64; e++) h = fmaf(t[r][e], w1[e * 64 + c], h);
    rv[r][c] = fmaxf(h, 0.f) * we[c];
    __syncthreads();
    if (c < 32) {
        float v = rv[r][c] + rv[r][c + 32];
#pragma unroll
        for (int off2 = 16; off2; off2 >>= 1) v += __shfl_down_sync(0xffffffffu, v, off2);
        if (c == 0) g_s1[row] = v;
    }
}

// ---------------- bitonic sort of s1 (desc, index asc tiebreak) ------------
__global__ void __launch_bounds__(1024, 1) ker_sort() {
    __shared__ float v[NP];
    __shared__ int   ix[NP];
    int tid = threadIdx.x;
    for (int i = tid; i < NP; i += 1024) {
        v[i] = g_s1[i]; ix[i] = i; g_first[i] = 0x7fffffff;
    }
    __syncthreads();
    for (int size = 2; size <= NP; size <<= 1) {
        for (int stride = size >> 1; stride > 0; stride >>= 1) {
#pragma unroll
            for (int q = 0; q < 2; q++) {
                int t = tid + q * 1024;
                int lo = ((t & ~(stride - 1)) << 1) | (t & (stride - 1));
                int hi = lo + stride;
                bool desc = ((lo & size) == 0);
                float av = v[lo], bv = v[hi];
                int   ai = ix[lo], bi = ix[hi];
                bool before = (av > bv) || (av == bv && ai < bi);
                if (desc ? !before : before) {
                    v[lo] = bv; v[hi] = av; ix[lo] = bi; ix[hi] = ai;
                }
            }
            __syncthreads();
        }
    }
    for (int i = tid; i < NSEQ; i += 1024) { g_ordv[i] = v[i]; g_ordi[i] = ix[i]; }
}

// ---------------- shared coefficient helper ---------------------------------
__device__ __forceinline__ float dcoef(int j, int k) {
    if (k == 0) return 1.f;
    return (j == 0 || j == k) ? 0.70710678118654752f : 0.57735026918962576f;
}
__device__ __forceinline__ float sigmul(float hg, float gg) {
    return __fdividef(hg, 1.f + __expf(-gg));
}
__device__ __forceinline__ void coefs_for(int k, float& a1, float& a2, float& a3,
                                          float& b1, float& b2, float& b3,
                                          float& c1, float& c2) {
    if (k >= 4) {
        a1 = a2 = a3 = 0.33333333333333333f;
        b1 = b2 = 0.33333333333333333f; b3 = 0.40824829046386302f;
        c1 = 0.40824829046386302f;      c2 = 0.5f;
    } else {
        float djA = (k >= 2) ? dcoef(k - 2, k) : 0.f;
        a1 = (k >= 3) ? djA * dcoef(k - 3, k) : 0.f;
        a2 = djA * djA;
        a3 = (k >= 2) ? djA * dcoef(k - 1, k) : 0.f;
        float djB = (k >= 1) ? dcoef(k - 1, k) : 0.f;
        b1 = (k >= 2) ? djB * dcoef(k - 2, k) : 0.f;
        b2 = djB * djB;
        b3 = (k >= 1) ? djB * dcoef(k, k) : 0.f;
        float djC = dcoef(k, k);
        c1 = (k >= 1) ? djC * dcoef(k - 1, k) : 0.f;
        c2 = djC * djC;
    }
}

// ------- speculative parallel scan: assume all-spec (sorted selection) ------
// No per-step barrier/reduction feedback; verifies its own assumption.
__global__ void __launch_bounds__(192, 1)
ker_spec(const float* __restrict__ bgraph, const float* __restrict__ bgate,
         const float* __restrict__ wedge, float* __restrict__ out, int out_size) {
    int tid = threadIdx.x, lane = tid & 31, wrp = tid >> 5;
    __shared__ float s_seq[NSEQ];
    __shared__ int   s_ordS[NSEQ];
    __shared__ float s_valS[NSEQ];
    __shared__ float s_pp[NSEQ][6];
    __shared__ int   s_bad;
    for (int i = tid; i < NSEQ; i += 192) {
        s_seq[i] = g_seqc[i]; s_ordS[i] = g_ordi[i]; s_valS[i] = g_ordv[i];
    }
    if (tid == 0) s_bad = 0;
    bool gpart = (tid < 128);
    int hcol = tid - 128;
    float r_bg = 0.f, r_bt = 0.f, r_weg = 0.f, r_weh = 0.f;
    if (gpart) { r_bg = bgraph[tid]; r_bt = bgate[tid]; r_weg = wedge[144 + tid]; }
    else       { r_weh = wedge[64 + hcol]; }
    __syncthreads();

    // streaming state: rows k-3..k in regs + 2-deep prefetch (rows k+1,k+2)
    float Gm3 = 0, Gm2 = 0, Gm1 = 0, Tm3 = 0, Tm2 = 0, Tm1 = 0, Hm1 = 0;
    float Gc, Tc, Hc = 0, Gp1, Tp1, Hp1 = 0, Gp2, Tp2, Hp2 = 0;
    if (gpart) {
        Gc  = g_Pg[(size_t)s_ordS[0] * 128 + tid]; Tc  = g_Pt[(size_t)s_ordS[0] * 128 + tid];
        Gp1 = g_Pg[(size_t)s_ordS[1] * 128 + tid]; Tp1 = g_Pt[(size_t)s_ordS[1] * 128 + tid];
        Gp2 = g_Pg[(size_t)s_ordS[2] * 128 + tid]; Tp2 = g_Pt[(size_t)s_ordS[2] * 128 + tid];
    } else {
        Gc = Tc = Gp1 = Tp1 = Gp2 = Tp2 = 0.f;
        Hc  = g_Ph[(size_t)s_ordS[0] * 64 + hcol];
        Hp1 = g_Ph[(size_t)s_ordS[1] * 64 + hcol];
        Hp2 = g_Ph[(size_t)s_ordS[2] * 64 + hcol];
    }
    float base = 0.f;

    for (int k = 0; k < NSEQ; k++) {
        float a1, a2, a3, b1, b2, b3, c1, c2;
        coefs_for(k, a1, a2, a3, b1, b2, b3, c1, c2);
        float t;
        if (gpart) {
            if (k >= 2) {
                float hgA = r_bg + a1 * Gm3 + a2 * Gm2 + a3 * Gm1;
                float ggA = r_bt + a1 * Tm3 + a2 * Tm2 + a3 * Tm1;
                base += sigmul(hgA, ggA);
            }
            float hgr = base;
            if (k >= 1) {
                float hgB = r_bg + b1 * Gm2 + b2 * Gm1 + b3 * Gc;
                float ggB = r_bt + b1 * Tm2 + b2 * Tm1 + b3 * Tc;
                hgr += sigmul(hgB, ggB);
            }
            {
                float hgC = r_bg + c1 * Gm1 + c2 * Gc;
                float ggC = r_bt + c1 * Tm1 + c2 * Tc;
                hgr += sigmul(hgC, ggC);
            }
            t = fmaxf(hgr, 0.f) * r_weg;
        } else {
            float hl = c1 * Hm1 + c2 * Hc;
            t = fmaxf(hl, 0.f) * r_weh;
        }
#pragma unroll
        for (int off = 16; off; off >>= 1) t += __shfl_down_sync(0xffffffffu, t, off);
        if (lane == 0) s_pp[k][wrp] = t;

        // shift window + advance prefetch (no barrier — per-thread state only)
        Gm3 = Gm2; Gm2 = Gm1; Gm1 = Gc;
        Tm3 = Tm2; Tm2 = Tm1; Tm1 = Tc;
        Hm1 = Hc;
        Gc = Gp1; Tc = Tp1; Hc = Hp1;
        Gp1 = Gp2; Tp1 = Tp2; Hp1 = Hp2;
        if (k + 3 < NSEQ) {
            int rn = s_ordS[k + 3];
            if (gpart) { Gp2 = g_Pg[(size_t)rn * 128 + tid]; Tp2 = g_Pt[(size_t)rn * 128 + tid]; }
            else       { Hp2 = g_Ph[(size_t)rn * 64 + hcol]; }
        } else { Gp2 = Tp2 = Hp2 = 0.f; }
    }
    __syncthreads();

    // phase 2: assemble c_k, verify speculation, publish results
    bool write_idx = (out_size >= NP * NSEQ + NSEQ);
    for (int k = tid; k < NSEQ; k += 192) {
        float c = s_seq[k]
                + ((s_pp[k][0] + s_pp[k][1]) + (s_pp[k][2] + s_pp[k][3]))
                + (s_pp[k][4] + s_pp[k][5]);
        g_cvals[k] = c;
        if (k >= 1 && s_valS[k] + c <= 1e-4f) s_bad = 1;
        g_first[s_ordS[k]] = k;
        if (write_idx) out[(size_t)NP * NSEQ + k] = (float)s_ordS[k];
    }
    __syncthreads();
    if (tid == 0) g_specok = s_bad ? 0 : 1;
}

// ---------------- sequential fallback (runs only if speculation failed) -----
__global__ void __launch_bounds__(128, 1)
ker_scanB(const float* __restrict__ bgraph, const float* __restrict__ bgate,
          const float* __restrict__ wedge, const float* __restrict__ bedgep,
          float* __restrict__ out, int out_size) {
    if (*(volatile int*)&g_specok) return;   // speculation held — nothing to do
    int tid = threadIdx.x, lane = tid & 31, wrp = tid >> 5;
    __shared__ float s_vals[NSEQ];
    __shared__ int   s_ord[NSEQ];
    __shared__ float s_seq[NSEQ];
    __shared__ int   s_sel[NSEQ];
    __shared__ float s_cred[2][4];
    for (int i = tid; i < NSEQ; i += 128) {
        s_vals[i] = g_ordv[i]; s_ord[i] = g_ordi[i]; s_seq[i] = g_seqc[i];
        g_first[g_ordi[i]] = 0x7fffffff;    // undo speculative g_first writes
    }
    if (tid < 8) s_cred[tid >> 2][tid & 3] = 0.f;
    float bedge = bedgep[0];
    bool hpart = (tid < 64);
    float r_bg = bgraph[tid], r_bt = bgate[tid], r_weg = wedge[144 + tid];
    float r_weh = hpart ? wedge[64 + tid] : 0.f;
    float base = 0.f;
    __syncthreads();

    float q2g = 0.f, q3g = 0.f, q2t = 0.f, q3t = 0.f;
    float Mg = 0.f, Mt = 0.f, Mh = 0.f;
    float pf0g, pf0t, pf0h = 0.f, pf1g, pf1t, pf1h = 0.f;
    int p = 0, minsel = 0x7fffffff;
    float sv = s_vals[0];
    int so = s_ord[0];
    {
        int so1 = s_ord[1];
        pf0g = g_Pg[(size_t)so  * 128 + tid]; pf0t = g_Pt[(size_t)so  * 128 + tid];
        pf1g = g_Pg[(size_t)so1 * 128 + tid]; pf1t = g_Pt[(size_t)so1 * 128 + tid];
        if (hpart) {
            pf0h = g_Ph[(size_t)so  * 64 + tid];
            pf1h = g_Ph[(size_t)so1 * 64 + tid];
        }
    }
    float t_spec, t_nospec;
    {
        float hgr = sigmul(r_bg + pf0g, r_bt + pf0t);
        float t0 = fmaxf(hgr, 0.f) * r_weg;
        if (hpart) t0 += fmaxf(pf0h, 0.f) * r_weh;
        t_spec = t0; t_nospec = t0;
    }

    for (int k = 0; k < NSEQ; k++) {
        int rb = k & 1, wb = rb ^ 1;
        float c = s_seq[k]
                + ((s_cred[rb][0] + s_cred[rb][1]) + (s_cred[rb][2] + s_cred[rb][3]));
        float lhs = (sv + c) + bedge;
        bool spec; int idx;
        if (minsel == 0x7fffffff || lhs > bedge) { spec = true;  idx = so; }
        else if (lhs < bedge)                    { spec = false; idx = minsel; }
        else { if (so < minsel) { spec = true; idx = so; } else { spec = false; idx = minsel; } }
        if (tid == 0) { g_cvals[k] = c; s_sel[k] = idx; if (spec) g_first[idx] = k; }

        float t   = spec ? t_spec : t_nospec;
        float q4g = spec ? pf0g : Mg;
        float q4t = spec ? pf0t : Mt;
        float q4h = spec ? pf0h : Mh;

        if (spec) {
            if (idx < minsel) { minsel = idx; Mg = pf0g; Mt = pf0t; Mh = pf0h; }
            p++;
            int pc = (p < 511) ? p : 511;
            int pn = (p + 1 < 511) ? p + 1 : 511;
            sv = s_vals[pc];
            so = s_ord[pc];
            pf0g = pf1g; pf0t = pf1t; pf0h = pf1h;
            int son = s_ord[pn];
            pf1g = g_Pg[(size_t)son * 128 + tid]; pf1t = g_Pt[(size_t)son * 128 + tid];
            if (hpart) pf1h = g_Ph[(size_t)son * 64 + tid];
        }

        float tr = t;
#pragma unroll
        for (int off = 16; off; off >>= 1) tr += __shfl_down_sync(0xffffffffu, tr, off);
        if (lane == 0) s_cred[wb][wrp] = tr;

        if (k < NSEQ - 1) {
            int kk = k + 1;
            float a1, a2, a3, b1, b2, b3, c1, c2;
            coefs_for(kk, a1, a2, a3, b1, b2, b3, c1, c2);
            if (kk >= 2) {
                float hgA = r_bg + a1 * q2g + a2 * q3g + a3 * q4g;
                float ggA = r_bt + a1 * q2t + a2 * q3t + a3 * q4t;
                base += sigmul(hgA, ggA);
            }
            float pBh = r_bg + b1 * q3g + b2 * q4g;
            float pBg = r_bt + b1 * q3t + b2 * q4t;
            float pCh = r_bg + c1 * q4g;
            float pCg = r_bt + c1 * q4t;
            {
                float hgr = (base + sigmul(pBh + b3 * pf0g, pBg + b3 * pf0t))
                          + sigmul(pCh + c2 * pf0g, pCg + c2 * pf0t);
                t_spec = fmaxf(hgr, 0.f) * r_weg;
                if (hpart) {
                    float hl = c1 * q4h + c2 * pf0h;
                    t_spec += fmaxf(hl, 0.f) * r_weh;
                }
            }
            {
                float hgr = (base + sigmul(pBh + b3 * Mg, pBg + b3 * Mt))
                          + sigmul(pCh + c2 * Mg, pCg + c2 * Mt);
                t_nospec = fmaxf(hgr, 0.f) * r_weg;
                if (hpart) {
                    float hl = c1 * q4h + c2 * Mh;
                    t_nospec += fmaxf(hl, 0.f) * r_weh;
                }
            }
            q2g = q3g; q3g = q4g;
            q2t = q3t; q3t = q4t;
        }
        __syncthreads();
    }
    if (out_size >= NP * NSEQ + NSEQ)
        for (int i = tid; i < NSEQ; i += 128)
            out[(size_t)NP * NSEQ + i] = (float)s_sel[i];
}

// ---------------- parallel score-matrix writeback ---------------------------
__global__ void ker_scores(const float* __restrict__ bedgep, float* __restrict__ out) {
    float bedge = bedgep[0];
    int i0 = blockIdx.x * 1024 + threadIdx.x * 4;
    int k0 = blockIdx.y * 8;
    float4 s1 = *(const float4*)&g_s1[i0];
    int4   fs = *(const int4*)&g_first[i0];
#pragma unroll
    for (int kk = 0; kk < 8; kk++) {
        int k = k0 + kk;
        float c = g_cvals[k];
        float4 vv;
        vv.x = (fs.x >= k) ? (s1.x + c) + bedge : bedge;
        vv.y = (fs.y >= k) ? (s1.y + c) + bedge : bedge;
        vv.z = (fs.z >= k) ? (s1.z + c) + bedge : bedge;
        vv.w = (fs.w >= k) ? (s1.w + c) + bedge : bedge;
        *(float4*)&out[(size_t)k * NP + i0] = vv;
    }
}

// ---------------- launch -----------------------------------------------------
extern "C" void kernel_launch(void* const* d_in, const int* in_sizes, int n_in,
                              void* d_out, int out_size) {
    const float* x      = (const float*)d_in[0];
    const float* f      = (const float*)d_in[1];
    const float* a      = (const float*)d_in[2];
    const float* d      = (const float*)d_in[3];
    const float* wfeat  = (const float*)d_in[4];
    const float* bfeat  = (const float*)d_in[5];
    const float* wg1    = (const float*)d_in[6];
    const float* wg2    = (const float*)d_in[7];
    const float* wgraph = (const float*)d_in[8];
    const float* bgraph = (const float*)d_in[9];
    const float* wgate  = (const float*)d_in[10];
    const float* bgate  = (const float*)d_in[11];
    const float* wedge  = (const float*)d_in[12];
    const float* bedge  = (const float*)d_in[13];
    const float* wseq   = (const float*)d_in[14];
    const float* bseq   = (const float*)d_in[15];
    float* out = (float*)d_out;

    static cudaStream_t s_aux = 0;
    static cudaEvent_t  ev_fork = 0, ev_join = 0;
    if (!s_aux) {
        cudaStreamCreateWithFlags(&s_aux, cudaStreamNonBlocking);
        cudaEventCreateWithFlags(&ev_fork, cudaEventDisableTiming);
        cudaEventCreateWithFlags(&ev_join, cudaEventDisableTiming);
    }

    ker_init<<<1024 + 32 + 64, 256>>>(f, wfeat, bfeat, x, wseq, bseq, wedge,
                                      wg2, wgraph, wgate);
    cudaEventRecord(ev_fork, 0);
    cudaStreamWaitEvent(s_aux, ev_fork, 0);
    ker_proj<<<NP / 8, 320, 0, s_aux>>>(wg2);        // overlaps with gemm chain
    cudaEventRecord(ev_join, s_aux);

    dim3 gg(NP / 128, KSPLIT);
    ker_gemm64<<<gg, 128>>>(d, 0); ker_reduce<<<NP * EE / 1024, 256>>>(0);
    ker_gemm64<<<gg, 128>>>(a, 1); ker_reduce<<<NP * EE / 1024, 256>>>(1);
    ker_gemm64<<<gg, 128>>>(d, 2);

    ker_h1s1<<<NP / 4, 256>>>(wg1, wedge);
    ker_sort<<<1, 1024>>>();
    cudaStreamWaitEvent(0, ev_join, 0);              // Pg/Pt/Ph ready
    ker_spec<<<1, 192>>>(bgraph, bgate, wedge, out, out_size);
    ker_scanB<<<1, 128>>>(bgraph, bgate, wedge, bedge, out, out_size);
    if (out_size >= NP * NSEQ)
        ker_scores<<<dim3(4, 64), 256>>>(bedge, out);
}

// round 13
// speedup vs baseline: 1.9032x; 1.9032x over previous
#include <cuda_runtime.h>
#include <math.h>

#define NP   4096
#define NSEQ 512
#define EE   64
#define GG   128
#define KSPLIT 16

// ---------------- scratch (device globals) ---------------------------------
__device__ float g_f [NP*EE];
__device__ float g_fr[NP*EE];
__device__ float g_T1[NP*EE];
__device__ float g_T2[NP*EE];
__device__ float g_part[KSPLIT*NP*EE];
__device__ float g_s1[NP];
__device__ float g_seqc[NSEQ];
__device__ float g_w2g[EE*GG];
__device__ float g_w2t[EE*GG];
__device__ float g_Pg[NP*GG];
__device__ float g_Pt[NP*GG];
__device__ float g_Ph[NP*EE];
__device__ float g_ordv[NSEQ];
__device__ int   g_ordi[NSEQ];
__device__ int   g_first[NP];
__device__ float g_cvals[NSEQ];

// ---------------- f32x2 packed helpers -------------------------------------
__device__ __forceinline__ unsigned long long pk2(float lo, float hi) {
    unsigned long long r;
    asm("mov.b64 %0, {%1, %2};" : "=l"(r) : "f"(lo), "f"(hi));
    return r;
}
__device__ __forceinline__ void fma2(unsigned long long& d, unsigned long long a,
                                     unsigned long long b) {
    asm("fma.rn.f32x2 %0, %1, %2, %0;" : "+l"(d) : "l"(a), "l"(b));
}
__device__ __forceinline__ float2 upk(unsigned long long v) {
    float2 f;
    asm("mov.b64 {%0, %1}, %2;" : "=f"(f.x), "=f"(f.y) : "l"(v));
    return f;
}

// ---------------- fused small-kernel pass: feat | seq | fusew ---------------
__global__ void ker_init(const float* __restrict__ f, const float* __restrict__ wf,
                         const float* __restrict__ bf, const float* __restrict__ x,
                         const float* __restrict__ ws, const float* __restrict__ bs,
                         const float* __restrict__ we, const float* __restrict__ w2,
                         const float* __restrict__ wg, const float* __restrict__ wt) {
    int tid = threadIdx.x;
    int b = blockIdx.x;
    if (b < 1024) {                         // ---- feat
        __shared__ float fs[4][20];
        int r = tid >> 6, c = tid & 63;
        if (tid < 80) fs[tid / 20][tid % 20] = f[b * 80 + tid];
        __syncthreads();
        int row = b * 4 + r;
        float acc = bf[c];
#pragma unroll
        for (int a = 0; a < 20; a++) acc = fmaf(fs[r][a], wf[a * 64 + c], acc);
        g_f [row * 64 + c] = acc;
        g_fr[row * 64 + c] = fmaxf(acc, 0.f);
    } else if (b < 1056) {                  // ---- seq
        int bb = b - 1024;
        __shared__ float xv[16][20];
        __shared__ float red[16][16];
        for (int i = tid; i < 320; i += 256) xv[i / 20][i % 20] = x[bb * 320 + i];
        __syncthreads();
        int kk = tid >> 4, s = tid & 15;
        float e = bs[s];
#pragma unroll
        for (int a = 0; a < 20; a++) e = fmaf(xv[kk][a], ws[a * 16 + s], e);
        red[kk][s] = fmaxf(e, 0.f) * we[128 + s];
        __syncthreads();
        if (s == 0) {
            float t = 0.f;
#pragma unroll
            for (int q = 0; q < 16; q++) t += red[kk][q];
            g_seqc[bb * 16 + kk] = t;
        }
    } else {                                 // ---- fusew
        int o = (b - 1056) * 256 + tid;
        int which = o >> 13;
        int q = o & 8191;
        int e = q >> 7, c = q & 127;
        const float* W = which ? wt : wg;
        float acc = 0.f;
#pragma unroll
        for (int m = 0; m < 64; m++) acc = fmaf(w2[e * 64 + m], W[m * 128 + c], acc);
        if (which) g_w2t[q] = acc; else g_w2g[q] = acc;
    }
}

// ---------------- projections: Pg = F@w2g, Pt = F@w2t, Ph = F@wgcn2 --------
__global__ void __launch_bounds__(320) ker_proj(const float* __restrict__ wgcn2) {
    __shared__ float rows[8][64];
    int tid = threadIdx.x;
    int r0 = blockIdx.x * 8;
    for (int i = tid; i < 512; i += 320)
        rows[i >> 6][i & 63] = g_f[(r0 + (i >> 6)) * 64 + (i & 63)];
    __syncthreads();
    const float* W; int c, stride; float* P; int pstride;
    if (tid < 128)      { W = g_w2g; c = tid;       stride = 128; P = g_Pg; pstride = 128; }
    else if (tid < 256) { W = g_w2t; c = tid - 128; stride = 128; P = g_Pt; pstride = 128; }
    else                { W = wgcn2; c = tid - 256; stride = 64;  P = g_Ph; pstride = 64;  }
    float acc[8] = {0,0,0,0,0,0,0,0};
#pragma unroll 8
    for (int e = 0; e < 64; e++) {
        float w = W[e * stride + c];
#pragma unroll
        for (int r = 0; r < 8; r++) acc[r] = fmaf(rows[r][e], w, acc[r]);
    }
#pragma unroll
    for (int r = 0; r < 8; r++) P[(size_t)(r0 + r) * pstride + c] = acc[r];
}

// -------- C_partial = A @ B  (split-K, f32x2, R3 layout + double buffer) ----
__global__ void __launch_bounds__(128) ker_gemm64(const float* __restrict__ A, int bsel) {
    const float* __restrict__ B = (bsel == 0) ? g_fr : ((bsel == 1) ? g_T1 : g_T2);
    __shared__ float As[2][16][132];
    __shared__ float Bs[2][16][64];
    int tid = threadIdx.x;
    int tx = tid & 7, ty = tid >> 3;
    int row0 = blockIdx.x * 128;
    int k0 = blockIdx.y * 256;
    int ar = tid >> 2;
    int ak = (tid & 3) * 4;
    int bk = tid >> 3;
    int bc = (tid & 7) * 8;

    unsigned long long acc[8][4];
#pragma unroll
    for (int i = 0; i < 8; i++)
#pragma unroll
        for (int j = 0; j < 4; j++) acc[i][j] = 0ull;

    float4 av[4], bv0, bv1;
#pragma unroll
    for (int q = 0; q < 4; q++)
        av[q] = *(const float4*)&A[(size_t)(row0 + ar + 32 * q) * 4096 + (k0 + ak)];
    bv0 = *(const float4*)&B[(size_t)(k0 + bk) * 64 + bc];
    bv1 = *(const float4*)&B[(size_t)(k0 + bk) * 64 + bc + 4];
#pragma unroll
    for (int q = 0; q < 4; q++) {
        int r = ar + 32 * q;
        As[0][ak + 0][r] = av[q].x; As[0][ak + 1][r] = av[q].y;
        As[0][ak + 2][r] = av[q].z; As[0][ak + 3][r] = av[q].w;
    }
    *(float4*)&Bs[0][bk][bc]     = bv0;
    *(float4*)&Bs[0][bk][bc + 4] = bv1;
    __syncthreads();

    for (int t = 0; t < 16; t++) {
        int cur = t & 1;
        if (t < 15) {
            int kn = k0 + (t + 1) * 16;
#pragma unroll
            for (int q = 0; q < 4; q++)
                av[q] = *(const float4*)&A[(size_t)(row0 + ar + 32 * q) * 4096 + (kn + ak)];
            bv0 = *(const float4*)&B[(size_t)(kn + bk) * 64 + bc];
            bv1 = *(const float4*)&B[(size_t)(kn + bk) * 64 + bc + 4];
        }
#pragma unroll
        for (int kk = 0; kk < 16; kk++) {
            float4 a0 = *(const float4*)&As[cur][kk][ty * 8];
            float4 a1 = *(const float4*)&As[cur][kk][ty * 8 + 4];
            float4 b0 = *(const float4*)&Bs[cur][kk][tx * 8];
            float4 b1 = *(const float4*)&Bs[cur][kk][tx * 8 + 4];
            unsigned long long bp[4];
            bp[0] = pk2(b0.x, b0.y); bp[1] = pk2(b0.z, b0.w);
            bp[2] = pk2(b1.x, b1.y); bp[3] = pk2(b1.z, b1.w);
            float ar8[8] = {a0.x, a0.y, a0.z, a0.w, a1.x, a1.y, a1.z, a1.w};
#pragma unroll
            for (int i = 0; i < 8; i++) {
                unsigned long long ap = pk2(ar8[i], ar8[i]);
#pragma unroll
                for (int j = 0; j < 4; j++) fma2(acc[i][j], ap, bp[j]);
            }
        }
        if (t < 15) {
            int nxt = cur ^ 1;
#pragma unroll
            for (int q = 0; q < 4; q++) {
                int r = ar + 32 * q;
                As[nxt][ak + 0][r] = av[q].x; As[nxt][ak + 1][r] = av[q].y;
                As[nxt][ak + 2][r] = av[q].z; As[nxt][ak + 3][r] = av[q].w;
            }
            *(float4*)&Bs[nxt][bk][bc]     = bv0;
            *(float4*)&Bs[nxt][bk][bc + 4] = bv1;
            __syncthreads();
        }
    }
    float* Cp = g_part + (size_t)blockIdx.y * (NP * EE);
#pragma unroll
    for (int i = 0; i < 8; i++) {
        int row = row0 + ty * 8 + i;
        float2 c0 = upk(acc[i][0]), c1 = upk(acc[i][1]);
        float2 c2 = upk(acc[i][2]), c3 = upk(acc[i][3]);
        float* p = &Cp[(size_t)row * 64 + tx * 8];
        *(float4*)p       = make_float4(c0.x, c0.y, c1.x, c1.y);
        *(float4*)(p + 4) = make_float4(c2.x, c2.y, c3.x, c3.y);
    }
}

// ---------------- split-K reduce (float4 vectorized) ------------------------
__global__ void ker_reduce(int csel) {
    float* C = (csel == 1) ? g_T2 : g_T1;
    int i = (blockIdx.x * 256 + threadIdx.x) * 4;
    float4 s = *(const float4*)&g_part[i];
#pragma unroll
    for (int q = 1; q < KSPLIT; q++) {
        float4 v = *(const float4*)&g_part[(size_t)q * (NP * EE) + i];
        s.x += v.x; s.y += v.y; s.z += v.z; s.w += v.w;
    }
    *(float4*)&C[i] = s;
}

// ------------- fused: reduce partials of GEMM3 + s1 computation -------------
__global__ void ker_h1s1(const float* __restrict__ w1, const float* __restrict__ we) {
    __shared__ float t[4][64];
    __shared__ float rv[4][64];
    int tid = threadIdx.x;
    int r = tid >> 6, c = tid & 63;
    int row = blockIdx.x * 4 + r;
    size_t off = (size_t)row * 64 + c;
    float s = 0.f;
#pragma unroll
    for (int q = 0; q < KSPLIT; q++) s += g_part[(size_t)q * (NP * EE) + off];
    t[r][c] = s;
    __syncthreads();
    float h = 0.f;
#pragma unroll
    for (int e = 0; e < 64; e++) h = fmaf(t[r][e], w1[e * 64 + c], h);
    rv[r][c] = fmaxf(h, 0.f) * we[c];
    __syncthreads();
    if (c < 32) {
        float v = rv[r][c] + rv[r][c + 32];
#pragma unroll
        for (int off2 = 16; off2; off2 >>= 1) v += __shfl_down_sync(0xffffffffu, v, off2);
        if (c == 0) g_s1[row] = v;
    }
}

// ---------------- bitonic sort of s1 (desc, index asc tiebreak) ------------
__global__ void __launch_bounds__(1024, 1) ker_sort() {
    __shared__ float v[NP];
    __shared__ int   ix[NP];
    int tid = threadIdx.x;
    for (int i = tid; i < NP; i += 1024) {
        v[i] = g_s1[i]; ix[i] = i; g_first[i] = 0x7fffffff;
    }
    __syncthreads();
    for (int size = 2; size <= NP; size <<= 1) {
        for (int stride = size >> 1; stride > 0; stride >>= 1) {
#pragma unroll
            for (int q = 0; q < 2; q++) {
                int t = tid + q * 1024;
                int lo = ((t & ~(stride - 1)) << 1) | (t & (stride - 1));
                int hi = lo + stride;
                bool desc = ((lo & size) == 0);
                float av = v[lo], bv = v[hi];
                int   ai = ix[lo], bi = ix[hi];
                bool before = (av > bv) || (av == bv && ai < bi);
                if (desc ? !before : before) {
                    v[lo] = bv; v[hi] = av; ix[lo] = bi; ix[hi] = ai;
                }
            }
            __syncthreads();
        }
    }
    for (int i = tid; i < NSEQ; i += 1024) { g_ordv[i] = v[i]; g_ordi[i] = ix[i]; }
}

// ---------------- recurrence (dual-variant speculative contributions) -------
__device__ __forceinline__ float dcoef(int j, int k) {
    if (k == 0) return 1.f;
    return (j == 0 || j == k) ? 0.70710678118654752f : 0.57735026918962576f;
}
__device__ __forceinline__ float sigmul(float hg, float gg) {
    return __fdividef(hg, 1.f + __expf(-gg));
}

__global__ void __launch_bounds__(128, 1)
ker_scanB(const float* __restrict__ bgraph, const float* __restrict__ bgate,
          const float* __restrict__ wedge, const float* __restrict__ bedgep,
          float* __restrict__ out, int out_size) {
    int tid = threadIdx.x, lane = tid & 31, wrp = tid >> 5;
    __shared__ float s_vals[NSEQ];
    __shared__ int   s_ord[NSEQ];
    __shared__ float s_seq[NSEQ];
    __shared__ int   s_sel[NSEQ];
    __shared__ float s_cred[2][4];
    for (int i = tid; i < NSEQ; i += 128) {
        s_vals[i] = g_ordv[i]; s_ord[i] = g_ordi[i]; s_seq[i] = g_seqc[i];
    }
    if (tid < 8) s_cred[tid >> 2][tid & 3] = 0.f;
    float bedge = bedgep[0];
    bool hpart = (tid < 64);
    float r_bg = bgraph[tid], r_bt = bgate[tid], r_weg = wedge[144 + tid];
    float r_weh = hpart ? wedge[64 + tid] : 0.f;
    float base = 0.f;
    __syncthreads();

    // ring rows (g/t): q2=row(k-2), q3=row(k-1); committed q4=row(k) each step
    float q2g = 0.f, q3g = 0.f, q2t = 0.f, q3t = 0.f;
    float Mg = 0.f, Mt = 0.f, Mh = 0.f;                  // cached minsel row
    float pf0g, pf0t, pf0h = 0.f, pf1g, pf1t, pf1h = 0.f; // depth-2 prefetch
    int p = 0, minsel = 0x7fffffff;
    float sv = s_vals[0];
    int so = s_ord[0];
    {
        int so1 = s_ord[1];
        pf0g = g_Pg[(size_t)so  * 128 + tid]; pf0t = g_Pt[(size_t)so  * 128 + tid];
        pf1g = g_Pg[(size_t)so1 * 128 + tid]; pf1t = g_Pt[(size_t)so1 * 128 + tid];
        if (hpart) {
            pf0h = g_Ph[(size_t)so  * 64 + tid];
            pf1h = g_Ph[(size_t)so1 * 64 + tid];
        }
    }
    // prologue: t variants for k=0 (coef: c1=0, c2=1; no A/B windows; spec forced)
    float t_spec, t_nospec;
    {
        float hg = r_bg + pf0g;
        float gg = r_bt + pf0t;
        float hgr = 0.f + sigmul(hg, gg);
        float t0 = fmaxf(hgr, 0.f) * r_weg;
        if (hpart) t0 += fmaxf(pf0h, 0.f) * r_weh;
        t_spec = t0; t_nospec = t0;
    }

    for (int k = 0; k < NSEQ; k++) {
        int rb = k & 1, wb = rb ^ 1;
        float c = s_seq[k]
                + ((s_cred[rb][0] + s_cred[rb][1]) + (s_cred[rb][2] + s_cred[rb][3]));
        // --- selection (same float comparison as full-score argmax)
        float lhs = (sv + c) + bedge;
        bool spec; int idx;
        if (minsel == 0x7fffffff || lhs > bedge) { spec = true;  idx = so; }
        else if (lhs < bedge)                    { spec = false; idx = minsel; }
        else { if (so < minsel) { spec = true; idx = so; } else { spec = false; idx = minsel; } }
        if (tid == 0) { g_cvals[k] = c; s_sel[k] = idx; if (spec) g_first[idx] = k; }

        // --- pick precomputed contribution + commit row k (registers only)
        float t   = spec ? t_spec : t_nospec;
        float q4g = spec ? pf0g : Mg;
        float q4t = spec ? pf0t : Mt;
        float q4h = spec ? pf0h : Mh;

        // --- advance candidate state
        if (spec) {
            if (idx < minsel) { minsel = idx; Mg = pf0g; Mt = pf0t; Mh = pf0h; }
            p++;
            int pc = (p < 511) ? p : 511;
            int pn = (p + 1 < 511) ? p + 1 : 511;
            sv = s_vals[pc];
            so = s_ord[pc];
            pf0g = pf1g; pf0t = pf1t; pf0h = pf1h;
            int son = s_ord[pn];
            pf1g = g_Pg[(size_t)son * 128 + tid]; pf1t = g_Pt[(size_t)son * 128 + tid];
            if (hpart) pf1h = g_Ph[(size_t)son * 64 + tid];
        }

        // --- reduce picked t (serial chain)
        float tr = t;
#pragma unroll
        for (int off = 16; off; off >>= 1) tr += __shfl_down_sync(0xffffffffu, tr, off);
        if (lane == 0) s_cred[wb][wrp] = tr;

        // --- precompute t variants for step k+1 (independent of the reduce)
        if (k < NSEQ - 1) {
            int kk = k + 1;
            float a1, a2, a3, b1, b2, b3, c1, c2;
            if (kk >= 4) {
                a1 = a2 = a3 = 0.33333333333333333f;
                b1 = b2 = 0.33333333333333333f; b3 = 0.40824829046386302f;
                c1 = 0.40824829046386302f;      c2 = 0.5f;
            } else {
                float djA = (kk >= 2) ? dcoef(kk - 2, kk) : 0.f;
                a1 = (kk >= 3) ? djA * dcoef(kk - 3, kk) : 0.f;
                a2 = djA * djA;
                a3 = (kk >= 2) ? djA * dcoef(kk - 1, kk) : 0.f;
                float djB = (kk >= 1) ? dcoef(kk - 1, kk) : 0.f;
                b1 = (kk >= 2) ? djB * dcoef(kk - 2, kk) : 0.f;
                b2 = djB * djB;
                b3 = (kk >= 1) ? djB * dcoef(kk, kk) : 0.f;
                float djC = dcoef(kk, kk);
                c1 = (kk >= 1) ? djC * dcoef(kk - 1, kk) : 0.f;
                c2 = djC * djC;
            }
            // window A(kk) uses rows kk-3..kk-1 = q2,q3,q4 — selection-independent
            if (kk >= 2) {
                float hgA = r_bg + a1 * q2g + a2 * q3g + a3 * q4g;
                float ggA = r_bt + a1 * q2t + a2 * q3t + a3 * q4t;
                base += sigmul(hgA, ggA);
            }
            // partials (candidate-independent prefixes, same fma association)
            float pBh = r_bg + b1 * q3g + b2 * q4g;
            float pBg = r_bt + b1 * q3t + b2 * q4t;
            float pCh = r_bg + c1 * q4g;
            float pCg = r_bt + c1 * q4t;
            {   // spec variant: candidate = pf0 (post-advance)
                float hgr = (base + sigmul(pBh + b3 * pf0g, pBg + b3 * pf0t))
                          + sigmul(pCh + c2 * pf0g, pCg + c2 * pf0t);
                t_spec = fmaxf(hgr, 0.f) * r_weg;
                if (hpart) {
                    float hl = c1 * q4h + c2 * pf0h;
                    t_spec += fmaxf(hl, 0.f) * r_weh;
                }
            }
            {   // nospec variant: candidate = M (post-update)
                float hgr = (base + sigmul(pBh + b3 * Mg, pBg + b3 * Mt))
                          + sigmul(pCh + c2 * Mg, pCg + c2 * Mt);
                t_nospec = fmaxf(hgr, 0.f) * r_weg;
                if (hpart) {
                    float hl = c1 * q4h + c2 * Mh;
                    t_nospec += fmaxf(hl, 0.f) * r_weh;
                }
            }
            // shift rings
            q2g = q3g; q3g = q4g;
            q2t = q3t; q3t = q4t;
        }
        __syncthreads();
    }
    if (out_size >= NP * NSEQ + NSEQ)
        for (int i = tid; i < NSEQ; i += 128)
            out[(size_t)NP * NSEQ + i] = (float)s_sel[i];
}

// ---------------- parallel score-matrix writeback ---------------------------
__global__ void ker_scores(const float* __restrict__ bedgep, float* __restrict__ out) {
    float bedge = bedgep[0];
    int i0 = blockIdx.x * 1024 + threadIdx.x * 4;
    int k0 = blockIdx.y * 8;
    float4 s1 = *(const float4*)&g_s1[i0];
    int4   fs = *(const int4*)&g_first[i0];
#pragma unroll
    for (int kk = 0; kk < 8; kk++) {
        int k = k0 + kk;
        float c = g_cvals[k];
        float4 vv;
        vv.x = (fs.x >= k) ? (s1.x + c) + bedge : bedge;
        vv.y = (fs.y >= k) ? (s1.y + c) + bedge : bedge;
        vv.z = (fs.z >= k) ? (s1.z + c) + bedge : bedge;
        vv.w = (fs.w >= k) ? (s1.w + c) + bedge : bedge;
        *(float4*)&out[(size_t)k * NP + i0] = vv;
    }
}

// ---------------- launch -----------------------------------------------------
extern "C" void kernel_launch(void* const* d_in, const int* in_sizes, int n_in,
                              void* d_out, int out_size) {
    const float* x      = (const float*)d_in[0];
    const float* f      = (const float*)d_in[1];
    const float* a      = (const float*)d_in[2];
    const float* d      = (const float*)d_in[3];
    const float* wfeat  = (const float*)d_in[4];
    const float* bfeat  = (const float*)d_in[5];
    const float* wg1    = (const float*)d_in[6];
    const float* wg2    = (const float*)d_in[7];
    const float* wgraph = (const float*)d_in[8];
    const float* bgraph = (const float*)d_in[9];
    const float* wgate  = (const float*)d_in[10];
    const float* bgate  = (const float*)d_in[11];
    const float* wedge  = (const float*)d_in[12];
    const float* bedge  = (const float*)d_in[13];
    const float* wseq   = (const float*)d_in[14];
    const float* bseq   = (const float*)d_in[15];
    float* out = (float*)d_out;

    // aux stream + events: created once on the first (uncaptured) call,
    // reused inside graph capture via event-edge fork/join.
    static cudaStream_t s_aux = 0;
    static cudaEvent_t  ev_fork = 0, ev_join = 0;
    if (!s_aux) {
        cudaStreamCreateWithFlags(&s_aux, cudaStreamNonBlocking);
        cudaEventCreateWithFlags(&ev_fork, cudaEventDisableTiming);
        cudaEventCreateWithFlags(&ev_join, cudaEventDisableTiming);
    }

    ker_init<<<1024 + 32 + 64, 256>>>(f, wfeat, bfeat, x, wseq, bseq, wedge,
                                      wg2, wgraph, wgate);
    cudaEventRecord(ev_fork, 0);
    cudaStreamWaitEvent(s_aux, ev_fork, 0);
    ker_proj<<<NP / 8, 320, 0, s_aux>>>(wg2);        // overlaps with gemm chain
    cudaEventRecord(ev_join, s_aux);

    dim3 gg(NP / 128, KSPLIT);
    ker_gemm64<<<gg, 128>>>(d, 0); ker_reduce<<<NP * EE / 1024, 256>>>(0);  // T1 = d @ relu(F)
    ker_gemm64<<<gg, 128>>>(a, 1); ker_reduce<<<NP * EE / 1024, 256>>>(1);  // T2 = a @ T1
    ker_gemm64<<<gg, 128>>>(d, 2);                                          // partials only

    ker_h1s1<<<NP / 4, 256>>>(wg1, wedge);   // fused reduce3 + s1
    ker_sort<<<1, 1024>>>();
    cudaStreamWaitEvent(0, ev_join, 0);      // scanB needs Pg/Pt/Ph
    ker_scanB<<<1, 128>>>(bgraph, bgate, wedge, bedge, out, out_size);
    if (out_size >= NP * NSEQ)
        ker_scores<<<dim3(4, 64), 256>>>(bedge, out);
}